// round 2
// baseline (speedup 1.0000x reference)
#include <cuda_runtime.h>
#include <cuda_bf16.h>

#define NN     30000
#define NE     480000
#define NT     6
#define DIM    128
#define NS     1024      // selection list length / slot capacity
#define CAP    256       // per-(combo,slot) bucket capacity (in-degree ~Poisson(16))
#define GR     16        // rows per block in final GEMM

// ---------------- device scratch (static: no allocations allowed) ------------
__device__ int    g_sel_id[NN];
__device__ int    g_sel_nodes[NS];
__device__ int    g_nsel;
__device__ float  g_w[4][DIM];        // W_p@att_src_p, W_p@att_dst_p, W_c@att_src_c, W_c@att_dst_c
__device__ float  g_bsum[DIM];        // b_p+b_c+b_l+b_r
__device__ float  g_a[4][NN];         // a_sp, a_dp, a_sc, a_dc  per node
__device__ int    g_gat_cnt[12][NS];
__device__ uint2  g_gat_buck[12][NS][CAP];   // {src, e(bits)}  ~25 MB
__device__ int    g_sage_cnt[NT][NS];
__device__ int    g_sage_buck[NT][NS][CAP];  // src             ~6 MB
__device__ float  g_U[NT][NS][512];          // {z_p | z_c | mean | x_v}  ~12.6 MB
__device__ float  g_res[NT * NS * DIM];      // fused conv output per slot ~3 MB

// ---------------- kernels ----------------------------------------------------

__global__ void k_init() {
    int i = blockIdx.x * blockDim.x + threadIdx.x;
    if (i < NN) g_sel_id[i] = -1;
    if (i < 12 * NS) ((int*)g_gat_cnt)[i] = 0;
    if (i < NT * NS) ((int*)g_sage_cnt)[i] = 0;
    if (i == 0) g_nsel = 0;
}

__global__ void k_sel(const int* __restrict__ s) {
    int i = blockIdx.x * blockDim.x + threadIdx.x;
    if (i >= NS) return;
    int node = s[i];
    if (atomicCAS(&g_sel_id[node], -1, -2) == -1) {
        int slot = atomicAdd(&g_nsel, 1);
        g_sel_nodes[slot] = node;
        __threadfence();
        g_sel_id[node] = slot;
    }
}

__global__ void k_weights(const float* __restrict__ Wp, const float* __restrict__ asp,
                          const float* __restrict__ adp, const float* __restrict__ bp,
                          const float* __restrict__ Wc, const float* __restrict__ asc,
                          const float* __restrict__ adc, const float* __restrict__ bc,
                          const float* __restrict__ bl, const float* __restrict__ br) {
    int k = threadIdx.x;  // 128 threads
    float s0 = 0.f, s1 = 0.f, s2 = 0.f, s3 = 0.f;
    const float* wpr = Wp + k * DIM;
    const float* wcr = Wc + k * DIM;
    for (int j = 0; j < DIM; ++j) {
        float wp = wpr[j], wc = wcr[j];
        s0 += wp * asp[j];
        s1 += wp * adp[j];
        s2 += wc * asc[j];
        s3 += wc * adc[j];
    }
    g_w[0][k] = s0; g_w[1][k] = s1; g_w[2][k] = s2; g_w[3][k] = s3;
    g_bsum[k] = bp[k] + bc[k] + bl[k] + br[k];
}

// per-node attention scalars: one warp per node
__global__ void k_a(const float4* __restrict__ x4) {
    int node = (blockIdx.x * blockDim.x + threadIdx.x) >> 5;
    int lane = threadIdx.x & 31;
    if (node >= NN) return;
    float4 xv = x4[(size_t)node * 32 + lane];
    float4 w0 = ((const float4*)g_w[0])[lane];
    float4 w1 = ((const float4*)g_w[1])[lane];
    float4 w2 = ((const float4*)g_w[2])[lane];
    float4 w3 = ((const float4*)g_w[3])[lane];
    float s0 = xv.x * w0.x + xv.y * w0.y + xv.z * w0.z + xv.w * w0.w;
    float s1 = xv.x * w1.x + xv.y * w1.y + xv.z * w1.z + xv.w * w1.w;
    float s2 = xv.x * w2.x + xv.y * w2.y + xv.z * w2.z + xv.w * w2.w;
    float s3 = xv.x * w3.x + xv.y * w3.y + xv.z * w3.z + xv.w * w3.w;
    for (int o = 16; o; o >>= 1) {
        s0 += __shfl_xor_sync(~0u, s0, o);
        s1 += __shfl_xor_sync(~0u, s1, o);
        s2 += __shfl_xor_sync(~0u, s2, o);
        s3 += __shfl_xor_sync(~0u, s3, o);
    }
    if (lane == 0) {
        g_a[0][node] = s0; g_a[1][node] = s1;
        g_a[2][node] = s2; g_a[3][node] = s3;
    }
}

// GAT edge filter: gridDim.y = combo (t*2+which), which 0=params _p, 1=params _c
__global__ void k_scan_gat(const int* __restrict__ ei) {
    int e = blockIdx.x * blockDim.x + threadIdx.x;
    if (e >= NE) return;
    int combo = blockIdx.y;
    int t = combo >> 1, which = combo & 1;
    const int* src_p = ei + (size_t)((t * 3 + which) * 2 + 0) * NE;
    const int* dst_p = ei + (size_t)((t * 3 + which) * 2 + 1) * NE;
    int dst = dst_p[e];
    int slot = g_sel_id[dst];
    if (slot >= 0) {
        int src = src_p[e];
        float ev = g_a[2 * which][src] + g_a[2 * which + 1][dst];
        ev = ev >= 0.f ? ev : 0.2f * ev;  // leaky_relu(0.2)
        int pos = atomicAdd(&g_gat_cnt[combo][slot], 1);
        if (pos < CAP)
            g_gat_buck[combo][slot][pos] = make_uint2((unsigned)src, __float_as_uint(ev));
    }
}

__global__ void k_scan_sage(const int* __restrict__ ei) {
    int e = blockIdx.x * blockDim.x + threadIdx.x;
    if (e >= NE) return;
    int t = blockIdx.y;
    const int* src_p = ei + (size_t)((t * 3 + 2) * 2 + 0) * NE;
    const int* dst_p = ei + (size_t)((t * 3 + 2) * 2 + 1) * NE;
    int dst = dst_p[e];
    int slot = g_sel_id[dst];
    if (slot >= 0) {
        int pos = atomicAdd(&g_sage_cnt[t][slot], 1);
        if (pos < CAP) g_sage_buck[t][slot][pos] = src_p[e];
    }
}

// GAT softmax + aggregation: one warp per (combo, slot). z = sum alpha * x[src]
__global__ void k_gat_agg(const float4* __restrict__ x4) {
    int combo = blockIdx.y;
    int warp = threadIdx.x >> 5, lane = threadIdx.x & 31;
    int slot = blockIdx.x * 8 + warp;
    if (slot >= g_nsel) return;
    int which = combo & 1, t = combo >> 1;
    int cnt = g_gat_cnt[combo][slot]; if (cnt > CAP) cnt = CAP;
    const uint2* buck = g_gat_buck[combo][slot];
    int v = g_sel_nodes[slot];
    float es = g_a[2 * which][v] + g_a[2 * which + 1][v];       // self-loop score
    es = es >= 0.f ? es : 0.2f * es;
    float m = es;
    for (int i = lane; i < cnt; i += 32)
        m = fmaxf(m, __uint_as_float(buck[i].y));
    for (int o = 16; o; o >>= 1) m = fmaxf(m, __shfl_xor_sync(~0u, m, o));
    float dsum = 0.f;
    for (int i = lane; i < cnt; i += 32)
        dsum += __expf(__uint_as_float(buck[i].y) - m);
    for (int o = 16; o; o >>= 1) dsum += __shfl_xor_sync(~0u, dsum, o);
    dsum += __expf(es - m);
    float inv = 1.f / dsum;
    float cs = __expf(es - m) * inv;
    float4 xv = x4[(size_t)v * 32 + lane];
    float4 acc = make_float4(cs * xv.x, cs * xv.y, cs * xv.z, cs * xv.w);
    for (int i = 0; i < cnt; ++i) {          // broadcast read of bucket entry
        uint2 b = buck[i];
        float c = __expf(__uint_as_float(b.y) - m) * inv;
        float4 xs = x4[(size_t)b.x * 32 + lane];
        acc.x += c * xs.x; acc.y += c * xs.y; acc.z += c * xs.z; acc.w += c * xs.w;
    }
    float4* dst = (float4*)&g_U[t][slot][which * DIM];
    dst[lane] = acc;
}

// SAGE mean + copy of x[v]: one warp per (t, slot)
__global__ void k_sage_agg(const float4* __restrict__ x4) {
    int t = blockIdx.y;
    int warp = threadIdx.x >> 5, lane = threadIdx.x & 31;
    int slot = blockIdx.x * 8 + warp;
    if (slot >= g_nsel) return;
    int cnt = g_sage_cnt[t][slot]; if (cnt > CAP) cnt = CAP;
    const int* buck = g_sage_buck[t][slot];
    float4 acc = make_float4(0.f, 0.f, 0.f, 0.f);
    for (int i = 0; i < cnt; ++i) {
        float4 xs = x4[(size_t)buck[i] * 32 + lane];
        acc.x += xs.x; acc.y += xs.y; acc.z += xs.z; acc.w += xs.w;
    }
    float invc = 1.f / (float)(cnt > 0 ? cnt : 1);
    acc.x *= invc; acc.y *= invc; acc.z *= invc; acc.w *= invc;
    int v = g_sel_nodes[slot];
    float4* um = (float4*)&g_U[t][slot][256];
    float4* ux = (float4*)&g_U[t][slot][384];
    um[lane] = acc;
    ux[lane] = x4[(size_t)v * 32 + lane];
}

// fused output GEMM: res[row,:] = (U[row,:] @ [Wp;Wc;Wl;Wr] + bsum) / 3
__global__ void __launch_bounds__(128) k_gemm(
        const float* __restrict__ Wp, const float* __restrict__ Wc,
        const float* __restrict__ Wl, const float* __restrict__ Wr) {
    __shared__ __align__(16) float Us[GR][DIM];
    int j = threadIdx.x;               // output column
    int row0 = blockIdx.x * GR;
    float acc[GR];
#pragma unroll
    for (int r = 0; r < GR; ++r) acc[r] = 0.f;
    const float* Ws[4] = {Wp, Wc, Wl, Wr};
    const float* Ubase = &g_U[0][0][0];
    for (int kt = 0; kt < 4; ++kt) {
        __syncthreads();
        for (int idx = j; idx < GR * 32; idx += DIM) {
            int r = idx >> 5, q = idx & 31;
            ((float4*)Us[r])[q] =
                ((const float4*)(Ubase + (size_t)(row0 + r) * 512 + kt * DIM))[q];
        }
        __syncthreads();
        const float* Wt = Ws[kt];
        for (int k = 0; k < DIM; k += 4) {
            float w0 = Wt[(k + 0) * DIM + j];
            float w1 = Wt[(k + 1) * DIM + j];
            float w2 = Wt[(k + 2) * DIM + j];
            float w3 = Wt[(k + 3) * DIM + j];
#pragma unroll
            for (int r = 0; r < GR; ++r) {
                float4 u = *(const float4*)&Us[r][k];
                acc[r] = fmaf(u.x, w0, fmaf(u.y, w1, fmaf(u.z, w2, fmaf(u.w, w3, acc[r]))));
            }
        }
    }
    float b = g_bsum[j] * (1.f / 3.f);
#pragma unroll
    for (int r = 0; r < GR; ++r)
        g_res[(size_t)(row0 + r) * DIM + j] = acc[r] * (1.f / 3.f) + b;
}

// out[t][i][:] = res[t][sel_id[s[i]]][:]
__global__ void k_gather(const int* __restrict__ s, float4* __restrict__ out4) {
    int idx = blockIdx.x * blockDim.x + threadIdx.x;     // over 6*1024*32 float4
    if (idx >= NT * NS * 32) return;
    int t = idx >> 15;
    int rem = idx & 32767;
    int i = rem >> 5, q = rem & 31;
    int slot = g_sel_id[s[i]];
    out4[idx] = ((const float4*)g_res)[(size_t)((t << 10) + slot) * 32 + q];
}

// ---------------- launch -----------------------------------------------------
extern "C" void kernel_launch(void* const* d_in, const int* in_sizes, int n_in,
                              void* d_out, int out_size) {
    const int*   s   = (const int*)d_in[0];
    // d_in[1] = t_s, d_in[2] = t_e : unused by the reference
    const int*   ei  = (const int*)d_in[3];
    const float* x   = (const float*)d_in[4];
    const float* Wp  = (const float*)d_in[5];
    const float* asp = (const float*)d_in[6];
    const float* adp = (const float*)d_in[7];
    const float* bp  = (const float*)d_in[8];
    const float* Wc  = (const float*)d_in[9];
    const float* asc = (const float*)d_in[10];
    const float* adc = (const float*)d_in[11];
    const float* bc  = (const float*)d_in[12];
    const float* Wl  = (const float*)d_in[13];
    const float* bl  = (const float*)d_in[14];
    const float* Wr  = (const float*)d_in[15];
    const float* br  = (const float*)d_in[16];
    const float4* x4 = (const float4*)x;

    k_init<<<(NN + 255) / 256, 256>>>();
    k_sel<<<4, 256>>>(s);
    k_weights<<<1, 128>>>(Wp, asp, adp, bp, Wc, asc, adc, bc, bl, br);
    k_a<<<(NN * 32 + 255) / 256, 256>>>(x4);
    {
        dim3 g((NE + 255) / 256, 12);
        k_scan_gat<<<g, 256>>>(ei);
    }
    {
        dim3 g((NE + 255) / 256, NT);
        k_scan_sage<<<g, 256>>>(ei);
    }
    {
        dim3 g(NS / 8, 12);
        k_gat_agg<<<g, 256>>>(x4);
    }
    {
        dim3 g(NS / 8, NT);
        k_sage_agg<<<g, 256>>>(x4);
    }
    k_gemm<<<(NT * NS) / GR, 128>>>(Wp, Wc, Wl, Wr);
    k_gather<<<(NT * NS * 32 + 255) / 256, 256>>>(s, (float4*)d_out);
}

// round 12
// speedup vs baseline: 1.1606x; 1.1606x over previous
#include <cuda_runtime.h>
#include <cuda_bf16.h>

#define NN     30000
#define NE     480000
#define NT     6
#define DIM    128
#define NS     1024      // selection list length / slot capacity
#define CAP    256       // per-(combo,slot) bucket capacity (in-degree ~Poisson(16))

// ---------------- device scratch (static: no allocations allowed) ------------
__device__ int    g_sel_id[NN];
__device__ int    g_sel_nodes[NS];
__device__ int    g_nsel;
__device__ float  g_w[4][DIM];        // W_p@att_src_p, W_p@att_dst_p, W_c@att_src_c, W_c@att_dst_c
__device__ float  g_bsum[DIM];        // b_p+b_c+b_l+b_r
__device__ float  g_a[4][NN];         // a_sp, a_dp, a_sc, a_dc  per node
__device__ int    g_gat_cnt[12][NS];
__device__ uint2  g_gat_buck[12][NS][CAP];   // {src, e(bits)}
__device__ int    g_sage_cnt[NT][NS];
__device__ int    g_sage_buck[NT][NS][CAP];  // src
__device__ float  g_U[NT][NS][512];          // {z_p | z_c | mean | x_v}
__device__ float  g_res[NT * NS * DIM];

// ---------------- kernels ----------------------------------------------------

__global__ void k_init() {
    int i = blockIdx.x * blockDim.x + threadIdx.x;
    if (i < NN) g_sel_id[i] = -1;
    if (i < 12 * NS) ((int*)g_gat_cnt)[i] = 0;
    if (i < NT * NS) ((int*)g_sage_cnt)[i] = 0;
    if (i == 0) g_nsel = 0;
}

__global__ void k_sel(const int* __restrict__ s) {
    int i = blockIdx.x * blockDim.x + threadIdx.x;
    if (i >= NS) return;
    int node = s[i];
    if (atomicCAS(&g_sel_id[node], -1, -2) == -1) {
        int slot = atomicAdd(&g_nsel, 1);
        g_sel_nodes[slot] = node;
        __threadfence();
        g_sel_id[node] = slot;
    }
}

__global__ void k_weights(const float* __restrict__ Wp, const float* __restrict__ asp,
                          const float* __restrict__ adp, const float* __restrict__ bp,
                          const float* __restrict__ Wc, const float* __restrict__ asc,
                          const float* __restrict__ adc, const float* __restrict__ bc,
                          const float* __restrict__ bl, const float* __restrict__ br) {
    int k = threadIdx.x;  // 128 threads
    float s0 = 0.f, s1 = 0.f, s2 = 0.f, s3 = 0.f;
    const float* wpr = Wp + k * DIM;
    const float* wcr = Wc + k * DIM;
    for (int j = 0; j < DIM; ++j) {
        float wp = wpr[j], wc = wcr[j];
        s0 += wp * asp[j];
        s1 += wp * adp[j];
        s2 += wc * asc[j];
        s3 += wc * adc[j];
    }
    g_w[0][k] = s0; g_w[1][k] = s1; g_w[2][k] = s2; g_w[3][k] = s3;
    g_bsum[k] = bp[k] + bc[k] + bl[k] + br[k];
}

// per-node attention scalars: smem-tiled GEMV, 32 nodes per block, no shuffles
#define AN 32
__global__ void __launch_bounds__(128) k_a(const float* __restrict__ x) {
    __shared__ float xs[AN][DIM + 1];    // stride 129 -> conflict-free column reads
    int node0 = blockIdx.x * AN;
    int tid = threadIdx.x;
    for (int i = tid; i < AN * DIM; i += 128) {
        int r = i >> 7, c = i & 127;
        int node = node0 + r;
        xs[r][c] = (node < NN) ? x[(size_t)node * DIM + c] : 0.f;
    }
    __syncthreads();
    int w = tid >> 5;        // which of 4 folded vectors
    int lane = tid & 31;     // node within tile
    const float* wv = g_w[w];
    float acc = 0.f;
#pragma unroll 8
    for (int k = 0; k < DIM; ++k)
        acc += xs[lane][k] * wv[k];      // wv[k] uniform -> broadcast load
    int node = node0 + lane;
    if (node < NN) g_a[w][node] = acc;
}

// fused edge scan over all 18 (t,kind) streams, 4 edges per thread via int4
__global__ void k_scan(const int* __restrict__ ei) {
    int g = blockIdx.y;                  // stream = t*3 + kind
    int t = g / 3, kind = g - t * 3;     // kind: 0=gat_p, 1=gat_c, 2=sage
    int e4 = blockIdx.x * blockDim.x + threadIdx.x;
    if (e4 >= NE / 4) return;
    const int4* dstv = (const int4*)(ei + ((size_t)g * 2 + 1) * NE);
    int4 d = dstv[e4];
    int sl[4];
    sl[0] = g_sel_id[d.x]; sl[1] = g_sel_id[d.y];
    sl[2] = g_sel_id[d.z]; sl[3] = g_sel_id[d.w];
    // skip only when ALL four are unmatched: sign(AND) = AND of signs
    if ((sl[0] & sl[1] & sl[2] & sl[3]) < 0) return;
    int4 sv = ((const int4*)(ei + (size_t)g * 2 * NE))[e4];
    int ds[4] = {d.x, d.y, d.z, d.w};
    int ss[4] = {sv.x, sv.y, sv.z, sv.w};
    if (kind == 2) {
#pragma unroll
        for (int u = 0; u < 4; ++u) {
            if (sl[u] >= 0) {
                int pos = atomicAdd(&g_sage_cnt[t][sl[u]], 1);
                if (pos < CAP) g_sage_buck[t][sl[u]][pos] = ss[u];
            }
        }
    } else {
        int which = kind;
        int combo = t * 2 + which;
        const float* as = g_a[2 * which];
        const float* ad = g_a[2 * which + 1];
#pragma unroll
        for (int u = 0; u < 4; ++u) {
            if (sl[u] >= 0) {
                float ev = as[ss[u]] + ad[ds[u]];
                ev = ev >= 0.f ? ev : 0.2f * ev;        // leaky_relu(0.2)
                int pos = atomicAdd(&g_gat_cnt[combo][sl[u]], 1);
                if (pos < CAP)
                    g_gat_buck[combo][sl[u]][pos] =
                        make_uint2((unsigned)ss[u], __float_as_uint(ev));
            }
        }
    }
}

// merged aggregation: y<12 -> GAT combo y ; y>=12 -> SAGE t=y-12. One warp/slot.
__global__ void __launch_bounds__(256) k_agg(const float4* __restrict__ x4) {
    int y = blockIdx.y;
    int warp = threadIdx.x >> 5, lane = threadIdx.x & 31;
    int slot = blockIdx.x * 8 + warp;
    if (slot >= g_nsel) return;

    if (y < 12) {
        int which = y & 1, t = y >> 1;
        int cnt = g_gat_cnt[y][slot]; if (cnt > CAP) cnt = CAP;
        const uint2* buck = g_gat_buck[y][slot];
        int v = g_sel_nodes[slot];
        float es = g_a[2 * which][v] + g_a[2 * which + 1][v];   // self-loop
        es = es >= 0.f ? es : 0.2f * es;
        float m = es;
        for (int i = lane; i < cnt; i += 32)
            m = fmaxf(m, __uint_as_float(buck[i].y));
        for (int o = 16; o; o >>= 1) m = fmaxf(m, __shfl_xor_sync(~0u, m, o));
        float dsum = 0.f;
        for (int i = lane; i < cnt; i += 32)
            dsum += __expf(__uint_as_float(buck[i].y) - m);
        for (int o = 16; o; o >>= 1) dsum += __shfl_xor_sync(~0u, dsum, o);
        dsum += __expf(es - m);
        float inv = 1.f / dsum;
        float cs = __expf(es - m) * inv;
        float4 xv = x4[(size_t)v * 32 + lane];
        float4 acc = make_float4(cs * xv.x, cs * xv.y, cs * xv.z, cs * xv.w);
        // 4-deep batched loads to expose MLP
        for (int i = 0; i < cnt; i += 4) {
            float4 xa[4]; float c[4];
#pragma unroll
            for (int u = 0; u < 4; ++u) {
                if (i + u < cnt) {
                    uint2 b = buck[i + u];
                    c[u]  = __expf(__uint_as_float(b.y) - m) * inv;
                    xa[u] = x4[(size_t)b.x * 32 + lane];
                }
            }
#pragma unroll
            for (int u = 0; u < 4; ++u) {
                if (i + u < cnt) {
                    acc.x += c[u] * xa[u].x; acc.y += c[u] * xa[u].y;
                    acc.z += c[u] * xa[u].z; acc.w += c[u] * xa[u].w;
                }
            }
        }
        ((float4*)&g_U[t][slot][which * DIM])[lane] = acc;
    } else {
        int t = y - 12;
        int cnt = g_sage_cnt[t][slot]; if (cnt > CAP) cnt = CAP;
        const int* buck = g_sage_buck[t][slot];
        float4 acc = make_float4(0.f, 0.f, 0.f, 0.f);
        for (int i = 0; i < cnt; i += 4) {
            float4 xa[4];
#pragma unroll
            for (int u = 0; u < 4; ++u)
                if (i + u < cnt) xa[u] = x4[(size_t)buck[i + u] * 32 + lane];
#pragma unroll
            for (int u = 0; u < 4; ++u)
                if (i + u < cnt) {
                    acc.x += xa[u].x; acc.y += xa[u].y;
                    acc.z += xa[u].z; acc.w += xa[u].w;
                }
        }
        float invc = 1.f / (float)(cnt > 0 ? cnt : 1);
        acc.x *= invc; acc.y *= invc; acc.z *= invc; acc.w *= invc;
        int v = g_sel_nodes[slot];
        ((float4*)&g_U[t][slot][256])[lane] = acc;
        ((float4*)&g_U[t][slot][384])[lane] = x4[(size_t)v * 32 + lane];
    }
}

// fused output GEMM, split-K x2: res = (U @ [Wp;Wc;Wl;Wr] + bsum)/3
// block: 32 rows x 128 cols, 512 threads = (col j, row-half, k-group)
#define GRR 32
__global__ void __launch_bounds__(512) k_gemm(
        const float* __restrict__ Wp, const float* __restrict__ Wc,
        const float* __restrict__ Wl, const float* __restrict__ Wr) {
    __shared__ __align__(16) float Us[2][GRR][DIM];   // 32 KB, one tile per k-group
    int tid = threadIdx.x;
    int j    = tid & 127;
    int half = (tid >> 7) & 1;
    int kg   = tid >> 8;
    int row0 = blockIdx.x * GRR;
    const float* Ws[4] = {Wp, Wc, Wl, Wr};
    const float* Ubase = &g_U[0][0][0];
    float acc[16];
#pragma unroll
    for (int r = 0; r < 16; ++r) acc[r] = 0.f;

    for (int it = 0; it < 2; ++it) {
        int kt = kg * 2 + it;
        // k-group's 256 threads load its 32x128 tile
        int t256 = tid & 255;
        for (int i = t256; i < GRR * 32; i += 256) {
            int r = i >> 5, q = i & 31;
            ((float4*)Us[kg][r])[q] =
                ((const float4*)(Ubase + (size_t)(row0 + r) * 512 + kt * DIM))[q];
        }
        __syncthreads();
        const float* Wt = Ws[kt];
        for (int k = 0; k < DIM; k += 4) {
            float w0 = Wt[(k + 0) * DIM + j];
            float w1 = Wt[(k + 1) * DIM + j];
            float w2 = Wt[(k + 2) * DIM + j];
            float w3 = Wt[(k + 3) * DIM + j];
#pragma unroll
            for (int r = 0; r < 16; ++r) {
                float4 u = *(const float4*)&Us[kg][half * 16 + r][k];  // broadcast
                acc[r] = fmaf(u.x, w0, fmaf(u.y, w1, fmaf(u.z, w2, fmaf(u.w, w3, acc[r]))));
            }
        }
        __syncthreads();
    }
    // cross-k-group reduction through Us[0] (reused as [32][128])
    float* red = &Us[0][0][0];
    if (kg == 1) {
#pragma unroll
        for (int r = 0; r < 16; ++r)
            red[(half * 16 + r) * DIM + j] = acc[r];
    }
    __syncthreads();
    if (kg == 0) {
        float b = g_bsum[j] * (1.f / 3.f);
#pragma unroll
        for (int r = 0; r < 16; ++r) {
            float v = (acc[r] + red[(half * 16 + r) * DIM + j]) * (1.f / 3.f) + b;
            g_res[(size_t)(row0 + half * 16 + r) * DIM + j] = v;
        }
    }
}

// out[t][i][:] = res[t][sel_id[s[i]]][:]
__global__ void k_gather(const int* __restrict__ s, float4* __restrict__ out4) {
    int idx = blockIdx.x * blockDim.x + threadIdx.x;     // over 6*1024*32 float4
    if (idx >= NT * NS * 32) return;
    int t = idx >> 15;
    int rem = idx & 32767;
    int i = rem >> 5, q = rem & 31;
    int slot = g_sel_id[s[i]];
    out4[idx] = ((const float4*)g_res)[(size_t)((t << 10) + slot) * 32 + q];
}

// ---------------- launch -----------------------------------------------------
extern "C" void kernel_launch(void* const* d_in, const int* in_sizes, int n_in,
                              void* d_out, int out_size) {
    const int*   s   = (const int*)d_in[0];
    // d_in[1] = t_s, d_in[2] = t_e : unused by the reference
    const int*   ei  = (const int*)d_in[3];
    const float* x   = (const float*)d_in[4];
    const float* Wp  = (const float*)d_in[5];
    const float* asp = (const float*)d_in[6];
    const float* adp = (const float*)d_in[7];
    const float* bp  = (const float*)d_in[8];
    const float* Wc  = (const float*)d_in[9];
    const float* asc = (const float*)d_in[10];
    const float* adc = (const float*)d_in[11];
    const float* bc  = (const float*)d_in[12];
    const float* Wl  = (const float*)d_in[13];
    const float* bl  = (const float*)d_in[14];
    const float* Wr  = (const float*)d_in[15];
    const float* br  = (const float*)d_in[16];
    const float4* x4 = (const float4*)x;

    k_init<<<(NN + 255) / 256, 256>>>();
    k_sel<<<4, 256>>>(s);
    k_weights<<<1, 128>>>(Wp, asp, adp, bp, Wc, asc, adc, bc, bl, br);
    k_a<<<(NN + AN - 1) / AN, 128>>>(x);
    {
        dim3 g((NE / 4 + 255) / 256, 18);
        k_scan<<<g, 256>>>(ei);
    }
    {
        dim3 g(NS / 8, 18);
        k_agg<<<g, 256>>>(x4);
    }
    k_gemm<<<(NT * NS) / GRR, 512>>>(Wp, Wc, Wl, Wr);
    k_gather<<<(NT * NS * 32 + 255) / 256, 256>>>(s, (float4*)d_out);
}